// round 5
// baseline (speedup 1.0000x reference)
#include <cuda_runtime.h>
#include <math.h>

#define NN 50000
#define NE 800000

// ---------------- device scratch (no allocations allowed) ----------------
__device__ float g_x0 [NN * 128];
__device__ float g_hin[NN * 128];
__device__ float g_pre[NN * 64];
__device__ float g_z1 [NN * 64];
__device__ float g_z2 [NN * 64];
__device__ float g_z3 [NN * 64];
__device__ float g_wt0a[128 * 128];
__device__ float g_wt0b[128 * 64];
__device__ float g_wt1a[64 * 64];
__device__ float g_wt1b[64 * 64];
__device__ float g_wt2a[64 * 64];
__device__ float g_wt2b[64 * 64];
__device__ float g_fc1t[320 * 64];
__device__ int   g_cnt[NN];
__device__ int   g_rowptr[NN + 1];
__device__ int   g_cursor[NN];
__device__ int   g_srt[NE];
__device__ float g_stats[128];   // [0:64) sum, [64:128) sumsq
__device__ float g_scale[64];
__device__ float g_shift[64];

// ---------------- utility kernels ----------------
__global__ void zero_int_kernel(int* p, int n) {
    int i = blockIdx.x * blockDim.x + threadIdx.x;
    if (i < n) p[i] = 0;
}
__global__ void zero_float_kernel(float* p, int n) {
    int i = blockIdx.x * blockDim.x + threadIdx.x;
    if (i < n) p[i] = 0.f;
}

__global__ void hist_kernel(const int* __restrict__ dst, int E) {
    int i = blockIdx.x * blockDim.x + threadIdx.x;
    if (i < E) atomicAdd(&g_cnt[dst[i]], 1);
}

// single-block exclusive scan over g_cnt -> g_rowptr (and g_cursor copy)
__global__ void scan_kernel(int N) {
    __shared__ int sums[1024];
    int t = threadIdx.x;
    int C = (N + 1023) >> 10;
    int beg = t * C;
    int end = min(beg + C, N);
    int s = 0;
    for (int i = beg; i < end; i++) s += g_cnt[i];
    sums[t] = s;
    __syncthreads();
    for (int off = 1; off < 1024; off <<= 1) {
        int v = (t >= off) ? sums[t - off] : 0;
        __syncthreads();
        sums[t] += v;
        __syncthreads();
    }
    int run = (t > 0) ? sums[t - 1] : 0;
    for (int i = beg; i < end; i++) {
        g_rowptr[i] = run;
        g_cursor[i] = run;
        run += g_cnt[i];
    }
    if (t == 1023) g_rowptr[N] = sums[1023];
}

__global__ void scatter_kernel(const int* __restrict__ src, const int* __restrict__ dst, int E) {
    int i = blockIdx.x * blockDim.x + threadIdx.x;
    if (i < E) {
        int p = atomicAdd(&g_cursor[dst[i]], 1);
        g_srt[p] = src[i];
    }
}

__global__ void transpose_kernel(const float* __restrict__ w, float* __restrict__ wt, int M, int K) {
    int i = blockIdx.x * blockDim.x + threadIdx.x;
    if (i < M * K) {
        int m = i / K, k = i - m * K;
        wt[k * M + m] = w[i];
    }
}

// x0[n] = concat(emb_deg[node_deg[n]], emb_lab[node_lab[n]])   (128 floats)
__global__ void embed_kernel(const float* __restrict__ ed, const float* __restrict__ el,
                             const int* __restrict__ nd, const int* __restrict__ nl, int N) {
    int i = blockIdx.x * blockDim.x + threadIdx.x;
    if (i >= N * 32) return;
    int n = i >> 5, q = i & 31;
    float4 v;
    if (q < 16) v = *(const float4*)&ed[nd[n] * 64 + q * 4];
    else        v = *(const float4*)&el[nl[n] * 64 + (q - 16) * 4];
    ((float4*)g_x0)[n * 32 + q] = v;
}

// h[n] = x[n] + sum_{e: dst==n} x[src[e]]   (CSR gather, warp per node)
template <int K>
__global__ void agg_kernel(const float* __restrict__ x, float* __restrict__ hout, int N) {
    int wid  = (blockIdx.x * blockDim.x + threadIdx.x) >> 5;
    int lane = threadIdx.x & 31;
    if (wid >= N) return;
    int beg = g_rowptr[wid], end = g_rowptr[wid + 1];
    if constexpr (K == 128) {
        float4 acc = *(const float4*)&x[wid * 128 + lane * 4];
        int e = beg;
        for (; e + 4 <= end; e += 4) {
            int s0 = g_srt[e], s1 = g_srt[e + 1], s2 = g_srt[e + 2], s3 = g_srt[e + 3];
            float4 v0 = *(const float4*)&x[s0 * 128 + lane * 4];
            float4 v1 = *(const float4*)&x[s1 * 128 + lane * 4];
            float4 v2 = *(const float4*)&x[s2 * 128 + lane * 4];
            float4 v3 = *(const float4*)&x[s3 * 128 + lane * 4];
            acc.x += (v0.x + v1.x) + (v2.x + v3.x);
            acc.y += (v0.y + v1.y) + (v2.y + v3.y);
            acc.z += (v0.z + v1.z) + (v2.z + v3.z);
            acc.w += (v0.w + v1.w) + (v2.w + v3.w);
        }
        for (; e < end; e++) {
            int s = g_srt[e];
            float4 v = *(const float4*)&x[s * 128 + lane * 4];
            acc.x += v.x; acc.y += v.y; acc.z += v.z; acc.w += v.w;
        }
        *(float4*)&hout[wid * 128 + lane * 4] = acc;
    } else {
        float2 acc = *(const float2*)&x[wid * 64 + lane * 2];
        int e = beg;
        for (; e + 4 <= end; e += 4) {
            int s0 = g_srt[e], s1 = g_srt[e + 1], s2 = g_srt[e + 2], s3 = g_srt[e + 3];
            float2 v0 = *(const float2*)&x[s0 * 64 + lane * 2];
            float2 v1 = *(const float2*)&x[s1 * 64 + lane * 2];
            float2 v2 = *(const float2*)&x[s2 * 64 + lane * 2];
            float2 v3 = *(const float2*)&x[s3 * 64 + lane * 2];
            acc.x += (v0.x + v1.x) + (v2.x + v3.x);
            acc.y += (v0.y + v1.y) + (v2.y + v3.y);
        }
        for (; e < end; e++) {
            int s = g_srt[e];
            float2 v = *(const float2*)&x[s * 64 + lane * 2];
            acc.x += v.x; acc.y += v.y;
        }
        *(float2*)&hout[wid * 64 + lane * 2] = acc;
    }
}

// GIN MLP: pre = (lrelu(h @ waT + ba)) @ wbT + bb    (weights pre-transposed to [K][M])
// 32-node tiles, register-tiled 8-warp GEMM, outputs pre-BN activations [N,64].
template <int K, int M1>
__global__ void __launch_bounds__(256) mlp_kernel(
    const float* __restrict__ hin,
    const float* __restrict__ wta, const float* __restrict__ ba,
    const float* __restrict__ wtb, const float* __restrict__ bb,
    float* __restrict__ out, int N)
{
    constexpr int TM = M1 / 32;
    __shared__ float A_s[K * 33];
    __shared__ float H_s[M1 * 33];
    const int tid = threadIdx.x;
    const int n0  = blockIdx.x * 32;

    for (int i = tid; i < 32 * K; i += 256) {
        int nl = i / K, k = i - nl * K;
        int n = n0 + nl;
        A_s[k * 33 + nl] = (n < N) ? hin[n * K + k] : 0.f;
    }
    __syncthreads();

    const int lane = tid & 31, wrp = tid >> 5;
    const int nb = wrp * 4;

    float acc[TM][4];
#pragma unroll
    for (int i = 0; i < TM; i++)
#pragma unroll
        for (int j = 0; j < 4; j++) acc[i][j] = 0.f;

#pragma unroll 4
    for (int k = 0; k < K; k++) {
        float a0 = A_s[k * 33 + nb + 0];
        float a1 = A_s[k * 33 + nb + 1];
        float a2 = A_s[k * 33 + nb + 2];
        float a3 = A_s[k * 33 + nb + 3];
        float wv[TM];
        if constexpr (TM == 4) {
            float4 w4 = *(const float4*)&wta[k * M1 + lane * 4];
            wv[0] = w4.x; wv[1] = w4.y; wv[2] = w4.z; wv[3] = w4.w;
        } else {
            float2 w2 = *(const float2*)&wta[k * M1 + lane * 2];
            wv[0] = w2.x; wv[1] = w2.y;
        }
#pragma unroll
        for (int i = 0; i < TM; i++) {
            acc[i][0] = fmaf(wv[i], a0, acc[i][0]);
            acc[i][1] = fmaf(wv[i], a1, acc[i][1]);
            acc[i][2] = fmaf(wv[i], a2, acc[i][2]);
            acc[i][3] = fmaf(wv[i], a3, acc[i][3]);
        }
    }

#pragma unroll
    for (int i = 0; i < TM; i++) {
        int m = lane * TM + i;
        float bv = ba[m];
#pragma unroll
        for (int j = 0; j < 4; j++) {
            float v = acc[i][j] + bv;
            H_s[m * 33 + nb + j] = (v > 0.f) ? v : 0.01f * v;
        }
    }
    __syncthreads();

    float a2c[2][4];
#pragma unroll
    for (int i = 0; i < 2; i++)
#pragma unroll
        for (int j = 0; j < 4; j++) a2c[i][j] = 0.f;

#pragma unroll 4
    for (int k = 0; k < M1; k++) {
        float a0 = H_s[k * 33 + nb + 0];
        float a1 = H_s[k * 33 + nb + 1];
        float a2 = H_s[k * 33 + nb + 2];
        float a3 = H_s[k * 33 + nb + 3];
        float2 w2 = *(const float2*)&wtb[k * 64 + lane * 2];
        a2c[0][0] = fmaf(w2.x, a0, a2c[0][0]);
        a2c[0][1] = fmaf(w2.x, a1, a2c[0][1]);
        a2c[0][2] = fmaf(w2.x, a2, a2c[0][2]);
        a2c[0][3] = fmaf(w2.x, a3, a2c[0][3]);
        a2c[1][0] = fmaf(w2.y, a0, a2c[1][0]);
        a2c[1][1] = fmaf(w2.y, a1, a2c[1][1]);
        a2c[1][2] = fmaf(w2.y, a2, a2c[1][2]);
        a2c[1][3] = fmaf(w2.y, a3, a2c[1][3]);
    }
    float b0 = bb[lane * 2], b1 = bb[lane * 2 + 1];
#pragma unroll
    for (int j = 0; j < 4; j++) {
        int n = n0 + nb + j;
        if (n < N) {
            float2 o;
            o.x = a2c[0][j] + b0;
            o.y = a2c[1][j] + b1;
            *(float2*)&out[n * 64 + lane * 2] = o;
        }
    }
}

// fc1: pre = concat(x0,z1,z2,z3) @ fc1_wT + fc1_b   (K=320 -> 64)
__global__ void __launch_bounds__(256) fc1_kernel(
    const float* __restrict__ x0, const float* __restrict__ z1,
    const float* __restrict__ z2, const float* __restrict__ z3,
    const float* __restrict__ wt, const float* __restrict__ fb,
    float* __restrict__ out, int N)
{
    __shared__ float A_s[320 * 33];
    const int tid = threadIdx.x;
    const int n0  = blockIdx.x * 32;

    for (int i = tid; i < 32 * 320; i += 256) {
        int nl = i / 320, k = i - nl * 320;
        int n = n0 + nl;
        float v = 0.f;
        if (n < N) {
            if (k < 128)      v = x0[n * 128 + k];
            else if (k < 192) v = z1[n * 64 + k - 128];
            else if (k < 256) v = z2[n * 64 + k - 192];
            else              v = z3[n * 64 + k - 256];
        }
        A_s[k * 33 + nl] = v;
    }
    __syncthreads();

    const int lane = tid & 31, wrp = tid >> 5;
    const int nb = wrp * 4;

    float acc[2][4];
#pragma unroll
    for (int i = 0; i < 2; i++)
#pragma unroll
        for (int j = 0; j < 4; j++) acc[i][j] = 0.f;

#pragma unroll 4
    for (int k = 0; k < 320; k++) {
        float a0 = A_s[k * 33 + nb + 0];
        float a1 = A_s[k * 33 + nb + 1];
        float a2 = A_s[k * 33 + nb + 2];
        float a3 = A_s[k * 33 + nb + 3];
        float2 w2 = *(const float2*)&wt[k * 64 + lane * 2];
        acc[0][0] = fmaf(w2.x, a0, acc[0][0]);
        acc[0][1] = fmaf(w2.x, a1, acc[0][1]);
        acc[0][2] = fmaf(w2.x, a2, acc[0][2]);
        acc[0][3] = fmaf(w2.x, a3, acc[0][3]);
        acc[1][0] = fmaf(w2.y, a0, acc[1][0]);
        acc[1][1] = fmaf(w2.y, a1, acc[1][1]);
        acc[1][2] = fmaf(w2.y, a2, acc[1][2]);
        acc[1][3] = fmaf(w2.y, a3, acc[1][3]);
    }
    float b0 = fb[lane * 2], b1 = fb[lane * 2 + 1];
#pragma unroll
    for (int j = 0; j < 4; j++) {
        int n = n0 + nb + j;
        if (n < N) {
            float2 o;
            o.x = acc[0][j] + b0;
            o.y = acc[1][j] + b1;
            *(float2*)&out[n * 64 + lane * 2] = o;
        }
    }
}

// per-channel sum / sumsq over rows [N,64]
__global__ void bn_stats_kernel(const float* __restrict__ x, int N) {
    __shared__ float ss[256], qq[256];
    int c  = threadIdx.x & 63;
    int rg = threadIdx.x >> 6;
    float s = 0.f, q = 0.f;
    for (int r = blockIdx.x * 4 + rg; r < N; r += gridDim.x * 4) {
        float v = x[r * 64 + c];
        s += v;
        q = fmaf(v, v, q);
    }
    ss[threadIdx.x] = s;
    qq[threadIdx.x] = q;
    __syncthreads();
    if (threadIdx.x < 64) {
        s = ss[threadIdx.x] + ss[threadIdx.x + 64] + ss[threadIdx.x + 128] + ss[threadIdx.x + 192];
        q = qq[threadIdx.x] + qq[threadIdx.x + 64] + qq[threadIdx.x + 128] + qq[threadIdx.x + 192];
        atomicAdd(&g_stats[c], s);
        atomicAdd(&g_stats[64 + c], q);
    }
}

__global__ void bn_final_kernel(const float* __restrict__ w, const float* __restrict__ b, int N) {
    int c = threadIdx.x;
    if (c < 64) {
        float m   = g_stats[c] / (float)N;
        float var = g_stats[64 + c] / (float)N - m * m;
        float inv = rsqrtf(var + 1e-5f);
        float a   = w[c] * inv;
        g_scale[c] = a;
        g_shift[c] = b[c] - m * a;
    }
}

__global__ void bn_apply_kernel(const float* __restrict__ pre, float* __restrict__ z, int N) {
    int i = blockIdx.x * blockDim.x + threadIdx.x;
    if (i >= N * 16) return;
    float4 v  = ((const float4*)pre)[i];
    int c0    = (i & 15) * 4;
    float4 sc = *(const float4*)&g_scale[c0];
    float4 sh = *(const float4*)&g_shift[c0];
    v.x = fmaf(v.x, sc.x, sh.x); v.x = (v.x > 0.f) ? v.x : 0.01f * v.x;
    v.y = fmaf(v.y, sc.y, sh.y); v.y = (v.y > 0.f) ? v.y : 0.01f * v.y;
    v.z = fmaf(v.z, sc.z, sh.z); v.z = (v.z > 0.f) ? v.z : 0.01f * v.z;
    v.w = fmaf(v.w, sc.w, sh.w); v.w = (v.w > 0.f) ? v.w : 0.01f * v.w;
    ((float4*)z)[i] = v;
}

// final: bn(fcbn) -> lrelu -> fc2 -> sigmoid. warp per node.
__global__ void final_kernel(const float* __restrict__ hpre,
                             const float* __restrict__ fc2w, const float* __restrict__ fc2b,
                             float* __restrict__ out, int N) {
    int w    = (blockIdx.x * blockDim.x + threadIdx.x) >> 5;
    int lane = threadIdx.x & 31;
    if (w >= N) return;
    float acc = 0.f;
#pragma unroll
    for (int k = lane; k < 64; k += 32) {
        float v = fmaf(hpre[w * 64 + k], g_scale[k], g_shift[k]);
        v = (v > 0.f) ? v : 0.01f * v;
        acc = fmaf(v, fc2w[k], acc);
    }
#pragma unroll
    for (int off = 16; off; off >>= 1) acc += __shfl_xor_sync(0xffffffffu, acc, off);
    if (lane == 0) out[w] = 1.f / (1.f + expf(-(acc + fc2b[0])));
}

// ---------------- launch ----------------
extern "C" void kernel_launch(void* const* d_in, const int* in_sizes, int n_in,
                              void* d_out, int out_size) {
    const float* emb_deg = (const float*)d_in[0];
    const float* emb_lab = (const float*)d_in[1];
    const float* w0a = (const float*)d_in[2];  const float* b0a = (const float*)d_in[3];
    const float* w0b = (const float*)d_in[4];  const float* b0b = (const float*)d_in[5];
    const float* bn0w = (const float*)d_in[6]; const float* bn0b = (const float*)d_in[7];
    const float* w1a = (const float*)d_in[8];  const float* b1a = (const float*)d_in[9];
    const float* w1b = (const float*)d_in[10]; const float* b1b = (const float*)d_in[11];
    const float* bn1w = (const float*)d_in[12]; const float* bn1b = (const float*)d_in[13];
    const float* w2a = (const float*)d_in[14]; const float* b2a = (const float*)d_in[15];
    const float* w2b = (const float*)d_in[16]; const float* b2b = (const float*)d_in[17];
    const float* bn2w = (const float*)d_in[18]; const float* bn2b = (const float*)d_in[19];
    const float* fc1w = (const float*)d_in[20]; const float* fc1b = (const float*)d_in[21];
    const float* fcbnw = (const float*)d_in[22]; const float* fcbnb = (const float*)d_in[23];
    const float* fc2w = (const float*)d_in[24]; const float* fc2b = (const float*)d_in[25];
    const int* node_deg = (const int*)d_in[26];
    const int* node_lab = (const int*)d_in[27];
    const int* edge = (const int*)d_in[28];

    const int N = in_sizes[26];
    const int E = in_sizes[28] / 2;
    const int* src  = edge;
    const int* dstp = edge + E;
    float* out = (float*)d_out;

    float *x0, *hin, *pre, *z1, *z2, *z3;
    float *wt0a, *wt0b, *wt1a, *wt1b, *wt2a, *wt2b, *fc1t, *stats;
    int* cnt;
    cudaGetSymbolAddress((void**)&x0,   g_x0);
    cudaGetSymbolAddress((void**)&hin,  g_hin);
    cudaGetSymbolAddress((void**)&pre,  g_pre);
    cudaGetSymbolAddress((void**)&z1,   g_z1);
    cudaGetSymbolAddress((void**)&z2,   g_z2);
    cudaGetSymbolAddress((void**)&z3,   g_z3);
    cudaGetSymbolAddress((void**)&wt0a, g_wt0a);
    cudaGetSymbolAddress((void**)&wt0b, g_wt0b);
    cudaGetSymbolAddress((void**)&wt1a, g_wt1a);
    cudaGetSymbolAddress((void**)&wt1b, g_wt1b);
    cudaGetSymbolAddress((void**)&wt2a, g_wt2a);
    cudaGetSymbolAddress((void**)&wt2b, g_wt2b);
    cudaGetSymbolAddress((void**)&fc1t, g_fc1t);
    cudaGetSymbolAddress((void**)&stats, g_stats);
    cudaGetSymbolAddress((void**)&cnt,  g_cnt);

    const int TB = 256;
    const int mlpBlocks  = (N + 31) / 32;
    const int warpBlocks = (N * 32 + TB - 1) / TB;

    // --- CSR build (by dst) ---
    zero_int_kernel<<<(N + TB - 1) / TB, TB>>>(cnt, N);
    hist_kernel<<<(E + TB - 1) / TB, TB>>>(dstp, E);
    scan_kernel<<<1, 1024>>>(N);
    scatter_kernel<<<(E + TB - 1) / TB, TB>>>(src, dstp, E);

    // --- weight transposes ---
    transpose_kernel<<<(128 * 128 + TB - 1) / TB, TB>>>(w0a, wt0a, 128, 128);
    transpose_kernel<<<(64 * 128 + TB - 1) / TB, TB>>>(w0b, wt0b, 64, 128);
    transpose_kernel<<<(64 * 64 + TB - 1) / TB, TB>>>(w1a, wt1a, 64, 64);
    transpose_kernel<<<(64 * 64 + TB - 1) / TB, TB>>>(w1b, wt1b, 64, 64);
    transpose_kernel<<<(64 * 64 + TB - 1) / TB, TB>>>(w2a, wt2a, 64, 64);
    transpose_kernel<<<(64 * 64 + TB - 1) / TB, TB>>>(w2b, wt2b, 64, 64);
    transpose_kernel<<<(64 * 320 + TB - 1) / TB, TB>>>(fc1w, fc1t, 64, 320);

    // --- embedding ---
    embed_kernel<<<warpBlocks, TB>>>(emb_deg, emb_lab, node_deg, node_lab, N);

    // --- layer 0 ---
    agg_kernel<128><<<warpBlocks, TB>>>(x0, hin, N);
    mlp_kernel<128, 128><<<mlpBlocks, 256>>>(hin, wt0a, b0a, wt0b, b0b, pre, N);
    zero_float_kernel<<<1, 128>>>(stats, 128);
    bn_stats_kernel<<<256, 256>>>(pre, N);
    bn_final_kernel<<<1, 64>>>(bn0w, bn0b, N);
    bn_apply_kernel<<<(N * 16 + TB - 1) / TB, TB>>>(pre, z1, N);

    // --- layer 1 ---
    agg_kernel<64><<<warpBlocks, TB>>>(z1, hin, N);
    mlp_kernel<64, 64><<<mlpBlocks, 256>>>(hin, wt1a, b1a, wt1b, b1b, pre, N);
    zero_float_kernel<<<1, 128>>>(stats, 128);
    bn_stats_kernel<<<256, 256>>>(pre, N);
    bn_final_kernel<<<1, 64>>>(bn1w, bn1b, N);
    bn_apply_kernel<<<(N * 16 + TB - 1) / TB, TB>>>(pre, z2, N);

    // --- layer 2 ---
    agg_kernel<64><<<warpBlocks, TB>>>(z2, hin, N);
    mlp_kernel<64, 64><<<mlpBlocks, 256>>>(hin, wt2a, b2a, wt2b, b2b, pre, N);
    zero_float_kernel<<<1, 128>>>(stats, 128);
    bn_stats_kernel<<<256, 256>>>(pre, N);
    bn_final_kernel<<<1, 64>>>(bn2w, bn2b, N);
    bn_apply_kernel<<<(N * 16 + TB - 1) / TB, TB>>>(pre, z3, N);

    // --- head: fc1 -> bn -> lrelu -> fc2 -> sigmoid ---
    fc1_kernel<<<mlpBlocks, 256>>>(x0, z1, z2, z3, fc1t, fc1b, pre, N);
    zero_float_kernel<<<1, 128>>>(stats, 128);
    bn_stats_kernel<<<256, 256>>>(pre, N);
    bn_final_kernel<<<1, 64>>>(fcbnw, fcbnb, N);
    final_kernel<<<warpBlocks, TB>>>(pre, fc2w, fc2b, out, N);
}

// round 6
// speedup vs baseline: 1.2523x; 1.2523x over previous
#include <cuda_runtime.h>
#include <math.h>

#define NN 50000
#define NE 800000

// ---------------- device scratch (no allocations allowed) ----------------
__device__ float g_hin [NN * 128];
__device__ float g_pre1[NN * 64];
__device__ float g_pre2[NN * 64];
__device__ float g_pre3[NN * 64];
__device__ float g_pre4[NN * 64];
__device__ float g_wt0a[128 * 128];
__device__ float g_wt0b[128 * 64];
__device__ float g_wt1a[64 * 64];
__device__ float g_wt1b[64 * 64];
__device__ float g_wt2a[64 * 64];
__device__ float g_wt2b[64 * 64];
__device__ float g_fc1t[320 * 64];
__device__ int   g_cnt[NN];
__device__ int   g_rowptr[NN + 1];
__device__ int   g_cursor[NN];
__device__ int   g_srt[NE];
__device__ int   g_bsum[256];
__device__ int   g_boff[256];
__device__ float g_stats[4 * 128];   // per BN: [0:64) sum, [64:128) sumsq

// ---------------- f32x2 packed helpers ----------------
__device__ __forceinline__ unsigned long long pk2(float x, float y) {
    unsigned long long r;
    asm("mov.b64 %0, {%1,%2};" : "=l"(r) : "f"(x), "f"(y));
    return r;
}
__device__ __forceinline__ void upk(unsigned long long v, float& x, float& y) {
    asm("mov.b64 {%0,%1}, %2;" : "=f"(x), "=f"(y) : "l"(v));
}
__device__ __forceinline__ void fma2(unsigned long long& d, unsigned long long a, unsigned long long b) {
    asm("fma.rn.f32x2 %0, %1, %2, %0;" : "+l"(d) : "l"(a), "l"(b));
}

// ---------------- prep: all weight transposes + zeroing, one kernel -------
__global__ void prep_kernel(const float* __restrict__ w0a, const float* __restrict__ w0b,
                            const float* __restrict__ w1a, const float* __restrict__ w1b,
                            const float* __restrict__ w2a, const float* __restrict__ w2b,
                            const float* __restrict__ fc1w, int N) {
    int i = blockIdx.x * blockDim.x + threadIdx.x;
    if (i < 16384) { int m = i >> 7, k = i & 127; g_wt0a[k * 128 + m] = w0a[i]; return; }
    i -= 16384;
    if (i < 8192)  { int m = i >> 7, k = i & 127; g_wt0b[k * 64 + m] = w0b[i]; return; }
    i -= 8192;
    if (i < 4096)  { int m = i >> 6, k = i & 63; g_wt1a[k * 64 + m] = w1a[i]; return; }
    i -= 4096;
    if (i < 4096)  { int m = i >> 6, k = i & 63; g_wt1b[k * 64 + m] = w1b[i]; return; }
    i -= 4096;
    if (i < 4096)  { int m = i >> 6, k = i & 63; g_wt2a[k * 64 + m] = w2a[i]; return; }
    i -= 4096;
    if (i < 4096)  { int m = i >> 6, k = i & 63; g_wt2b[k * 64 + m] = w2b[i]; return; }
    i -= 4096;
    if (i < 20480) { int m = i / 320, k = i - m * 320; g_fc1t[k * 64 + m] = fc1w[i]; return; }
    i -= 20480;
    if (i < 512)   { g_stats[i] = 0.f; return; }
    i -= 512;
    if (i < N) g_cnt[i] = 0;
}

// ---------------- CSR build ----------------
__global__ void hist_kernel(const int* __restrict__ dst, int E) {
    int i = blockIdx.x * blockDim.x + threadIdx.x;
    if (i < E) atomicAdd(&g_cnt[dst[i]], 1);
}

__global__ void scan_part(int N) {
    __shared__ int sm[256];
    int t = threadIdx.x, idx = blockIdx.x * 256 + t;
    sm[t] = (idx < N) ? g_cnt[idx] : 0;
    __syncthreads();
    for (int o = 128; o; o >>= 1) { if (t < o) sm[t] += sm[t + o]; __syncthreads(); }
    if (t == 0) g_bsum[blockIdx.x] = sm[0];
}

__global__ void scan_top(int B) {
    __shared__ int sm[256];
    int t = threadIdx.x;
    sm[t] = (t < B) ? g_bsum[t] : 0;
    __syncthreads();
    for (int o = 1; o < 256; o <<= 1) {
        int u = (t >= o) ? sm[t - o] : 0;
        __syncthreads();
        sm[t] += u;
        __syncthreads();
    }
    g_boff[t] = (t > 0) ? sm[t - 1] : 0;
}

__global__ void scan_apply(int N) {
    __shared__ int sm[256];
    int t = threadIdx.x, idx = blockIdx.x * 256 + t;
    int v = (idx < N) ? g_cnt[idx] : 0;
    sm[t] = v;
    __syncthreads();
    for (int o = 1; o < 256; o <<= 1) {
        int u = (t >= o) ? sm[t - o] : 0;
        __syncthreads();
        sm[t] += u;
        __syncthreads();
    }
    int excl = sm[t] - v + g_boff[blockIdx.x];
    if (idx < N) {
        g_rowptr[idx] = excl;
        g_cursor[idx] = excl;
        if (idx == N - 1) g_rowptr[N] = excl + v;
    }
}

__global__ void scatter_kernel(const int* __restrict__ src, const int* __restrict__ dst, int E) {
    int i = blockIdx.x * blockDim.x + threadIdx.x;
    if (i < E) {
        int p = atomicAdd(&g_cursor[dst[i]], 1);
        g_srt[p] = src[i];
    }
}

// ---------------- layer-0 aggregation straight from L1-resident tables ----
__global__ void agg0_kernel(const float* __restrict__ ed, const float* __restrict__ el,
                            const int* __restrict__ ndeg, const int* __restrict__ nlab,
                            float* __restrict__ hout, int N) {
    int wid  = (blockIdx.x * blockDim.x + threadIdx.x) >> 5;
    int lane = threadIdx.x & 31;
    if (wid >= N) return;
    const float* tbl    = (lane < 16) ? ed : el;
    const int*   idxarr = (lane < 16) ? ndeg : nlab;
    const int    offi   = (lane & 15) * 4;

    float4 acc = *(const float4*)&tbl[idxarr[wid] * 64 + offi];
    int beg = g_rowptr[wid], end = g_rowptr[wid + 1];
    int e = beg;
    for (; e + 4 <= end; e += 4) {
        int s0 = g_srt[e], s1 = g_srt[e + 1], s2 = g_srt[e + 2], s3 = g_srt[e + 3];
        int i0 = idxarr[s0], i1 = idxarr[s1], i2 = idxarr[s2], i3 = idxarr[s3];
        float4 v0 = *(const float4*)&tbl[i0 * 64 + offi];
        float4 v1 = *(const float4*)&tbl[i1 * 64 + offi];
        float4 v2 = *(const float4*)&tbl[i2 * 64 + offi];
        float4 v3 = *(const float4*)&tbl[i3 * 64 + offi];
        acc.x += (v0.x + v1.x) + (v2.x + v3.x);
        acc.y += (v0.y + v1.y) + (v2.y + v3.y);
        acc.z += (v0.z + v1.z) + (v2.z + v3.z);
        acc.w += (v0.w + v1.w) + (v2.w + v3.w);
    }
    for (; e < end; e++) {
        int i0 = idxarr[g_srt[e]];
        float4 v = *(const float4*)&tbl[i0 * 64 + offi];
        acc.x += v.x; acc.y += v.y; acc.z += v.z; acc.w += v.w;
    }
    *(float4*)&hout[wid * 128 + lane * 4] = acc;
}

// ---------------- aggregation with fused BN+lrelu of previous layer -------
__global__ void aggbn_kernel(const float* __restrict__ pre,
                             const float* __restrict__ bnw, const float* __restrict__ bnb,
                             float* __restrict__ hout, int N, int bnidx) {
    __shared__ float sc[64], sh[64];
    if (threadIdx.x < 64) {
        int c = threadIdx.x;
        float m   = g_stats[bnidx * 128 + c] / (float)N;
        float var = g_stats[bnidx * 128 + 64 + c] / (float)N - m * m;
        float inv = rsqrtf(var + 1e-5f);
        float a   = bnw[c] * inv;
        sc[c] = a;
        sh[c] = bnb[c] - m * a;
    }
    __syncthreads();
    int wid  = (blockIdx.x * blockDim.x + threadIdx.x) >> 5;
    int lane = threadIdx.x & 31;
    if (wid >= N) return;
    float a0 = sc[lane * 2], a1 = sc[lane * 2 + 1];
    float c0 = sh[lane * 2], c1 = sh[lane * 2 + 1];
#define BNR(v) { v.x = fmaf(v.x, a0, c0); v.x = fmaxf(v.x, 0.01f * v.x); \
                 v.y = fmaf(v.y, a1, c1); v.y = fmaxf(v.y, 0.01f * v.y); }
    float2 acc = *(const float2*)&pre[wid * 64 + lane * 2];
    BNR(acc);
    int beg = g_rowptr[wid], end = g_rowptr[wid + 1];
    int e = beg;
    for (; e + 4 <= end; e += 4) {
        int s0 = g_srt[e], s1 = g_srt[e + 1], s2 = g_srt[e + 2], s3 = g_srt[e + 3];
        float2 v0 = *(const float2*)&pre[s0 * 64 + lane * 2];
        float2 v1 = *(const float2*)&pre[s1 * 64 + lane * 2];
        float2 v2 = *(const float2*)&pre[s2 * 64 + lane * 2];
        float2 v3 = *(const float2*)&pre[s3 * 64 + lane * 2];
        BNR(v0); BNR(v1); BNR(v2); BNR(v3);
        acc.x += (v0.x + v1.x) + (v2.x + v3.x);
        acc.y += (v0.y + v1.y) + (v2.y + v3.y);
    }
    for (; e < end; e++) {
        float2 v = *(const float2*)&pre[g_srt[e] * 64 + lane * 2];
        BNR(v);
        acc.x += v.x; acc.y += v.y;
    }
#undef BNR
    *(float2*)&hout[wid * 64 + lane * 2] = acc;
}

// ---------------- GIN MLP: 64-node tiles, f32x2 FFMA, fused BN stats ------
template <int K, int M1>
__global__ void __launch_bounds__(256) mlp_kernel(
    const float* __restrict__ hin,
    const float* __restrict__ wta, const float* __restrict__ ba,
    const float* __restrict__ wtb, const float* __restrict__ bb,
    float* __restrict__ out, int N, int bnidx)
{
    constexpr int TMa = M1 / 32;
    extern __shared__ float smem[];
    float* A_s = smem;                 // K  * 66
    float* H_s = smem + K * 66;        // M1 * 66
    float* RS  = H_s + M1 * 66;        // 512
    float* RQ  = RS + 512;             // 512

    const int tid = threadIdx.x;
    const int n0  = blockIdx.x * 64;

    for (int i = tid; i < 64 * K; i += 256) {
        int nl = i / K, k = i - nl * K;
        int n = n0 + nl;
        A_s[k * 66 + nl] = (n < N) ? hin[n * K + k] : 0.f;
    }
    __syncthreads();

    const int lane = tid & 31, wrp = tid >> 5;
    const int nb = wrp * 8;

    unsigned long long acc[TMa][4];
#pragma unroll
    for (int i = 0; i < TMa; i++)
#pragma unroll
        for (int p = 0; p < 4; p++) acc[i][p] = 0ULL;

#pragma unroll 8
    for (int k = 0; k < K; k++) {
        const float* row = &A_s[k * 66 + nb];
        unsigned long long a0 = *(const unsigned long long*)(row + 0);
        unsigned long long a1 = *(const unsigned long long*)(row + 2);
        unsigned long long a2 = *(const unsigned long long*)(row + 4);
        unsigned long long a3 = *(const unsigned long long*)(row + 6);
        if constexpr (TMa == 4) {
            float4 w4 = *(const float4*)&wta[k * M1 + lane * 4];
            unsigned long long w0 = pk2(w4.x, w4.x), w1 = pk2(w4.y, w4.y);
            unsigned long long w2 = pk2(w4.z, w4.z), w3 = pk2(w4.w, w4.w);
            fma2(acc[0][0], w0, a0); fma2(acc[0][1], w0, a1); fma2(acc[0][2], w0, a2); fma2(acc[0][3], w0, a3);
            fma2(acc[1][0], w1, a0); fma2(acc[1][1], w1, a1); fma2(acc[1][2], w1, a2); fma2(acc[1][3], w1, a3);
            fma2(acc[2][0], w2, a0); fma2(acc[2][1], w2, a1); fma2(acc[2][2], w2, a2); fma2(acc[2][3], w2, a3);
            fma2(acc[3][0], w3, a0); fma2(acc[3][1], w3, a1); fma2(acc[3][2], w3, a2); fma2(acc[3][3], w3, a3);
        } else {
            float2 wv = *(const float2*)&wta[k * M1 + lane * 2];
            unsigned long long w0 = pk2(wv.x, wv.x), w1 = pk2(wv.y, wv.y);
            fma2(acc[0][0], w0, a0); fma2(acc[0][1], w0, a1); fma2(acc[0][2], w0, a2); fma2(acc[0][3], w0, a3);
            fma2(acc[1][0], w1, a0); fma2(acc[1][1], w1, a1); fma2(acc[1][2], w1, a2); fma2(acc[1][3], w1, a3);
        }
    }

#pragma unroll
    for (int i = 0; i < TMa; i++) {
        int m = lane * TMa + i;
        float bv = ba[m];
#pragma unroll
        for (int p = 0; p < 4; p++) {
            float x, y;
            upk(acc[i][p], x, y);
            x += bv; y += bv;
            x = fmaxf(x, 0.01f * x);
            y = fmaxf(y, 0.01f * y);
            *(unsigned long long*)&H_s[m * 66 + nb + 2 * p] = pk2(x, y);
        }
    }
    __syncthreads();

    unsigned long long c2[2][4];
#pragma unroll
    for (int i = 0; i < 2; i++)
#pragma unroll
        for (int p = 0; p < 4; p++) c2[i][p] = 0ULL;

#pragma unroll 8
    for (int k = 0; k < M1; k++) {
        const float* row = &H_s[k * 66 + nb];
        unsigned long long a0 = *(const unsigned long long*)(row + 0);
        unsigned long long a1 = *(const unsigned long long*)(row + 2);
        unsigned long long a2 = *(const unsigned long long*)(row + 4);
        unsigned long long a3 = *(const unsigned long long*)(row + 6);
        float2 wv = *(const float2*)&wtb[k * 64 + lane * 2];
        unsigned long long w0 = pk2(wv.x, wv.x), w1 = pk2(wv.y, wv.y);
        fma2(c2[0][0], w0, a0); fma2(c2[0][1], w0, a1); fma2(c2[0][2], w0, a2); fma2(c2[0][3], w0, a3);
        fma2(c2[1][0], w1, a0); fma2(c2[1][1], w1, a1); fma2(c2[1][2], w1, a2); fma2(c2[1][3], w1, a3);
    }

    float b0 = bb[lane * 2], b1 = bb[lane * 2 + 1];
    float s0 = 0.f, q0 = 0.f, s1 = 0.f, q1 = 0.f;
#pragma unroll
    for (int p = 0; p < 4; p++) {
        float x0, x1, y0, y1;
        upk(c2[0][p], x0, x1);
        upk(c2[1][p], y0, y1);
        int na = n0 + nb + 2 * p;
        if (na < N) {
            float o0 = x0 + b0, o1 = y0 + b1;
            *(float2*)&out[na * 64 + lane * 2] = make_float2(o0, o1);
            s0 += o0; q0 = fmaf(o0, o0, q0);
            s1 += o1; q1 = fmaf(o1, o1, q1);
        }
        if (na + 1 < N) {
            float o0 = x1 + b0, o1 = y1 + b1;
            *(float2*)&out[(na + 1) * 64 + lane * 2] = make_float2(o0, o1);
            s0 += o0; q0 = fmaf(o0, o0, q0);
            s1 += o1; q1 = fmaf(o1, o1, q1);
        }
    }
    RS[wrp * 64 + lane * 2] = s0; RS[wrp * 64 + lane * 2 + 1] = s1;
    RQ[wrp * 64 + lane * 2] = q0; RQ[wrp * 64 + lane * 2 + 1] = q1;
    __syncthreads();
    if (tid < 128) {
        int c = tid & 63;
        const float* P = (tid >= 64) ? RQ : RS;
        float v = 0.f;
#pragma unroll
        for (int w = 0; w < 8; w++) v += P[w * 64 + c];
        atomicAdd(&g_stats[bnidx * 128 + ((tid >= 64) ? 64 : 0) + c], v);
    }
}

// ---------------- fc1: concat(emb, bnrelu(pre1..3)) @ fc1^T, fused stats --
__global__ void __launch_bounds__(256) fc1_kernel(
    const float* __restrict__ ed, const float* __restrict__ el,
    const int* __restrict__ ndeg, const int* __restrict__ nlab,
    const float* __restrict__ pre1, const float* __restrict__ pre2, const float* __restrict__ pre3,
    const float* __restrict__ bn0w, const float* __restrict__ bn0b,
    const float* __restrict__ bn1w, const float* __restrict__ bn1b,
    const float* __restrict__ bn2w, const float* __restrict__ bn2b,
    const float* __restrict__ wt, const float* __restrict__ fb,
    float* __restrict__ out, int N)
{
    extern __shared__ float smem[];
    float* A_s = smem;                 // 320*66 = 21120
    float* RS  = A_s + 21120;          // 512
    float* RQ  = RS + 512;             // 512
    float* sc  = RQ + 512;             // 192
    float* sh  = sc + 192;             // 192

    const int tid = threadIdx.x;
    if (tid < 192) {
        int l = tid >> 6, c = tid & 63;
        const float* w = (l == 0) ? bn0w : ((l == 1) ? bn1w : bn2w);
        const float* b = (l == 0) ? bn0b : ((l == 1) ? bn1b : bn2b);
        float m   = g_stats[l * 128 + c] / (float)N;
        float var = g_stats[l * 128 + 64 + c] / (float)N - m * m;
        float inv = rsqrtf(var + 1e-5f);
        float a   = w[c] * inv;
        sc[tid] = a;
        sh[tid] = b[c] - m * a;
    }
    __syncthreads();

    const int n0 = blockIdx.x * 64;
    for (int i = tid; i < 64 * 320; i += 256) {
        int nl = i / 320, k = i - nl * 320;
        int n = n0 + nl;
        float v = 0.f;
        if (n < N) {
            if (k < 64)       v = ed[ndeg[n] * 64 + k];
            else if (k < 128) v = el[nlab[n] * 64 + (k - 64)];
            else {
                int l = (k - 128) >> 6, c = (k - 128) & 63;
                const float* pr = (l == 0) ? pre1 : ((l == 1) ? pre2 : pre3);
                float p = fmaf(pr[n * 64 + c], sc[l * 64 + c], sh[l * 64 + c]);
                v = fmaxf(p, 0.01f * p);
            }
        }
        A_s[k * 66 + nl] = v;
    }
    __syncthreads();

    const int lane = tid & 31, wrp = tid >> 5;
    const int nb = wrp * 8;

    unsigned long long c2[2][4];
#pragma unroll
    for (int i = 0; i < 2; i++)
#pragma unroll
        for (int p = 0; p < 4; p++) c2[i][p] = 0ULL;

#pragma unroll 8
    for (int k = 0; k < 320; k++) {
        const float* row = &A_s[k * 66 + nb];
        unsigned long long a0 = *(const unsigned long long*)(row + 0);
        unsigned long long a1 = *(const unsigned long long*)(row + 2);
        unsigned long long a2 = *(const unsigned long long*)(row + 4);
        unsigned long long a3 = *(const unsigned long long*)(row + 6);
        float2 wv = *(const float2*)&wt[k * 64 + lane * 2];
        unsigned long long w0 = pk2(wv.x, wv.x), w1 = pk2(wv.y, wv.y);
        fma2(c2[0][0], w0, a0); fma2(c2[0][1], w0, a1); fma2(c2[0][2], w0, a2); fma2(c2[0][3], w0, a3);
        fma2(c2[1][0], w1, a0); fma2(c2[1][1], w1, a1); fma2(c2[1][2], w1, a2); fma2(c2[1][3], w1, a3);
    }

    float b0 = fb[lane * 2], b1 = fb[lane * 2 + 1];
    float s0 = 0.f, q0 = 0.f, s1 = 0.f, q1 = 0.f;
#pragma unroll
    for (int p = 0; p < 4; p++) {
        float x0, x1, y0, y1;
        upk(c2[0][p], x0, x1);
        upk(c2[1][p], y0, y1);
        int na = n0 + nb + 2 * p;
        if (na < N) {
            float o0 = x0 + b0, o1 = y0 + b1;
            *(float2*)&out[na * 64 + lane * 2] = make_float2(o0, o1);
            s0 += o0; q0 = fmaf(o0, o0, q0);
            s1 += o1; q1 = fmaf(o1, o1, q1);
        }
        if (na + 1 < N) {
            float o0 = x1 + b0, o1 = y1 + b1;
            *(float2*)&out[(na + 1) * 64 + lane * 2] = make_float2(o0, o1);
            s0 += o0; q0 = fmaf(o0, o0, q0);
            s1 += o1; q1 = fmaf(o1, o1, q1);
        }
    }
    RS[wrp * 64 + lane * 2] = s0; RS[wrp * 64 + lane * 2 + 1] = s1;
    RQ[wrp * 64 + lane * 2] = q0; RQ[wrp * 64 + lane * 2 + 1] = q1;
    __syncthreads();
    if (tid < 128) {
        int c = tid & 63;
        const float* P = (tid >= 64) ? RQ : RS;
        float v = 0.f;
#pragma unroll
        for (int w = 0; w < 8; w++) v += P[w * 64 + c];
        atomicAdd(&g_stats[3 * 128 + ((tid >= 64) ? 64 : 0) + c], v);
    }
}

// ---------------- final head: bn -> lrelu -> fc2 -> sigmoid ----------------
__global__ void final_kernel(const float* __restrict__ hpre,
                             const float* __restrict__ bnw, const float* __restrict__ bnb,
                             const float* __restrict__ fc2w, const float* __restrict__ fc2b,
                             float* __restrict__ out, int N) {
    __shared__ float sc[64], sh[64], w2s[64];
    if (threadIdx.x < 64) {
        int c = threadIdx.x;
        float m   = g_stats[3 * 128 + c] / (float)N;
        float var = g_stats[3 * 128 + 64 + c] / (float)N - m * m;
        float inv = rsqrtf(var + 1e-5f);
        float a   = bnw[c] * inv;
        sc[c]  = a;
        sh[c]  = bnb[c] - m * a;
        w2s[c] = fc2w[c];
    }
    __syncthreads();
    int wid  = (blockIdx.x * blockDim.x + threadIdx.x) >> 5;
    int lane = threadIdx.x & 31;
    if (wid >= N) return;
    float2 v = *(const float2*)&hpre[wid * 64 + lane * 2];
    float x = fmaf(v.x, sc[lane * 2], sh[lane * 2]);       x = fmaxf(x, 0.01f * x);
    float y = fmaf(v.y, sc[lane * 2 + 1], sh[lane * 2 + 1]); y = fmaxf(y, 0.01f * y);
    float acc = fmaf(x, w2s[lane * 2], y * w2s[lane * 2 + 1]);
#pragma unroll
    for (int off = 16; off; off >>= 1) acc += __shfl_xor_sync(0xffffffffu, acc, off);
    if (lane == 0) out[wid] = 1.f / (1.f + expf(-(acc + fc2b[0])));
}

// ---------------- launch ----------------
extern "C" void kernel_launch(void* const* d_in, const int* in_sizes, int n_in,
                              void* d_out, int out_size) {
    const float* emb_deg = (const float*)d_in[0];
    const float* emb_lab = (const float*)d_in[1];
    const float* w0a = (const float*)d_in[2];  const float* b0a = (const float*)d_in[3];
    const float* w0b = (const float*)d_in[4];  const float* b0b = (const float*)d_in[5];
    const float* bn0w = (const float*)d_in[6]; const float* bn0b = (const float*)d_in[7];
    const float* w1a = (const float*)d_in[8];  const float* b1a = (const float*)d_in[9];
    const float* w1b = (const float*)d_in[10]; const float* b1b = (const float*)d_in[11];
    const float* bn1w = (const float*)d_in[12]; const float* bn1b = (const float*)d_in[13];
    const float* w2a = (const float*)d_in[14]; const float* b2a = (const float*)d_in[15];
    const float* w2b = (const float*)d_in[16]; const float* b2b = (const float*)d_in[17];
    const float* bn2w = (const float*)d_in[18]; const float* bn2b = (const float*)d_in[19];
    const float* fc1w = (const float*)d_in[20]; const float* fc1b = (const float*)d_in[21];
    const float* fcbnw = (const float*)d_in[22]; const float* fcbnb = (const float*)d_in[23];
    const float* fc2w = (const float*)d_in[24]; const float* fc2b = (const float*)d_in[25];
    const int* node_deg = (const int*)d_in[26];
    const int* node_lab = (const int*)d_in[27];
    const int* edge = (const int*)d_in[28];

    const int N = in_sizes[26];
    const int E = in_sizes[28] / 2;
    const int* src  = edge;
    const int* dstp = edge + E;
    float* out = (float*)d_out;

    float *hin, *pre1, *pre2, *pre3, *pre4;
    float *wt0a, *wt0b, *wt1a, *wt1b, *wt2a, *wt2b, *fc1t;
    cudaGetSymbolAddress((void**)&hin,  g_hin);
    cudaGetSymbolAddress((void**)&pre1, g_pre1);
    cudaGetSymbolAddress((void**)&pre2, g_pre2);
    cudaGetSymbolAddress((void**)&pre3, g_pre3);
    cudaGetSymbolAddress((void**)&pre4, g_pre4);
    cudaGetSymbolAddress((void**)&wt0a, g_wt0a);
    cudaGetSymbolAddress((void**)&wt0b, g_wt0b);
    cudaGetSymbolAddress((void**)&wt1a, g_wt1a);
    cudaGetSymbolAddress((void**)&wt1b, g_wt1b);
    cudaGetSymbolAddress((void**)&wt2a, g_wt2a);
    cudaGetSymbolAddress((void**)&wt2b, g_wt2b);
    cudaGetSymbolAddress((void**)&fc1t, g_fc1t);

    const int TB = 256;
    const int mlpBlocks  = (N + 63) / 64;
    const int warpBlocks = (N * 32 + TB - 1) / TB;
    const int scanBlocks = (N + 255) / 256;

    const int SM_MLP0 = (128 * 66 + 128 * 66 + 1024) * 4;   // 71680
    const int SM_MLP1 = (64 * 66 + 64 * 66 + 1024) * 4;     // 37888
    const int SM_FC1  = (21120 + 1024 + 384) * 4;           // 90112
    cudaFuncSetAttribute(mlp_kernel<128, 128>, cudaFuncAttributeMaxDynamicSharedMemorySize, SM_MLP0);
    cudaFuncSetAttribute(mlp_kernel<64, 64>,   cudaFuncAttributeMaxDynamicSharedMemorySize, SM_MLP1);
    cudaFuncSetAttribute(fc1_kernel,           cudaFuncAttributeMaxDynamicSharedMemorySize, SM_FC1);

    // --- prep: transposes + zero stats + zero cnt (1 launch) ---
    const int prepTotal = 61440 + 512 + N;
    prep_kernel<<<(prepTotal + TB - 1) / TB, TB>>>(w0a, w0b, w1a, w1b, w2a, w2b, fc1w, N);

    // --- CSR build (by dst), multi-block scan ---
    hist_kernel<<<(E + TB - 1) / TB, TB>>>(dstp, E);
    scan_part<<<scanBlocks, 256>>>(N);
    scan_top<<<1, 256>>>(scanBlocks);
    scan_apply<<<scanBlocks, 256>>>(N);
    scatter_kernel<<<(E + TB - 1) / TB, TB>>>(src, dstp, E);

    // --- layer 0 (tables -> agg -> mlp w/ fused stats) ---
    agg0_kernel<<<warpBlocks, TB>>>(emb_deg, emb_lab, node_deg, node_lab, hin, N);
    mlp_kernel<128, 128><<<mlpBlocks, 256, SM_MLP0>>>(hin, wt0a, b0a, wt0b, b0b, pre1, N, 0);

    // --- layer 1 ---
    aggbn_kernel<<<warpBlocks, TB>>>(pre1, bn0w, bn0b, hin, N, 0);
    mlp_kernel<64, 64><<<mlpBlocks, 256, SM_MLP1>>>(hin, wt1a, b1a, wt1b, b1b, pre2, N, 1);

    // --- layer 2 ---
    aggbn_kernel<<<warpBlocks, TB>>>(pre2, bn1w, bn1b, hin, N, 1);
    mlp_kernel<64, 64><<<mlpBlocks, 256, SM_MLP1>>>(hin, wt2a, b2a, wt2b, b2b, pre3, N, 2);

    // --- head ---
    fc1_kernel<<<mlpBlocks, 256, SM_FC1>>>(emb_deg, emb_lab, node_deg, node_lab,
                                           pre1, pre2, pre3,
                                           bn0w, bn0b, bn1w, bn1b, bn2w, bn2b,
                                           fc1t, fc1b, pre4, N);
    final_kernel<<<warpBlocks, TB>>>(pre4, fcbnw, fcbnb, fc2w, fc2b, out, N);
}